// round 13
// baseline (speedup 1.0000x reference)
#include <cuda_runtime.h>
#include <cuda_fp16.h>
#include <cstdint>

#define BATCH 16
#define CDIM  768
#define NSEQ  576
#define NHEAD 12
#define HDIM  64
#define BH    (BATCH*NHEAD)     // 192
#define MROWS (BATCH*NSEQ)      // 9216
#define K3    (3*CDIM)          // 2304
#define K2CAT 2304              // GEMM2 concatenated K (3 x 768)

// ---------------- static device scratch ----------------
__device__ __align__(128) float  g_qkv[(size_t)MROWS * K3];        // 85 MB
__device__ __align__(128) __half g_a2[(size_t)MROWS * K2CAT];      // attn out split 42.5 MB
__device__ __align__(128) __half g_b2[(size_t)CDIM  * K2CAT];      // w_proj split 3.4 MB
__device__ unsigned long long g_qbits[BH * NSEQ];
__device__ unsigned long long g_kbits[BH * NSEQ];
__device__ float              g_sq[BH];
__device__ float              g_sk[BH];
__device__ __align__(16) signed char g_v8t[(size_t)BH * HDIM * NSEQ];
__device__ float              g_vinv[BH * HDIM];

// ---------------- helpers ----------------
#define MMA16816(d, a, b0_, b1_) \
    asm volatile("mma.sync.aligned.m16n8k16.row.col.f32.f16.f16.f32 " \
        "{%0,%1,%2,%3}, {%4,%5,%6,%7}, {%8,%9}, {%0,%1,%2,%3};" \
        : "+f"((d)[0]),"+f"((d)[1]),"+f"((d)[2]),"+f"((d)[3]) \
        : "r"((a)[0]),"r"((a)[1]),"r"((a)[2]),"r"((a)[3]), "r"(b0_),"r"(b1_))

#define FMA_X2(acc, a, b) \
    asm("fma.rn.f32x2 %0, %1, %2, %0;" : "+l"(acc) : "l"(a), "l"(b))

__device__ __forceinline__ float ull_lo(unsigned long long v) {
    return __uint_as_float((unsigned)v);
}
__device__ __forceinline__ float ull_hi(unsigned long long v) {
    return __uint_as_float((unsigned)(v >> 32));
}

#define RP 40   // smem row pitch in fp16 elements (GEMM2)

// =====================================================================
// GEMM 1: exact fp32 via packed fma.rn.f32x2 (2 FMAs/instr, bit-exact fp32).
// qkv[m, j] = sum_c x[b,c,n] * w_qkv[j,c].  128x128 tile, BK=8, 256 thr.
// A staged DUPLICATED in smem: As2[k][2m]=As2[k][2m+1]=A[m]  ->
// one 8B load = packed (a,a); B pairs are naturally contiguous 8B.
// =====================================================================
__global__ __launch_bounds__(256) void gemm_qkv_kernel(const float* __restrict__ x,
                                                       const float* __restrict__ w) {
    __shared__ float As2[8][256];    // duplicated pairs, 8 KB
    __shared__ float Bs[8][128];     // 4 KB
    const int tid  = threadIdx.x;
    const int row0 = blockIdx.x * 128;
    const int col0 = blockIdx.y * 128;
    const int tx = tid & 15, ty = tid >> 4;

    const int ia   = tid & 127;
    const int kb   = tid >> 7;
    const int arow = row0 + ia;
    const int ab   = arow / NSEQ;
    const int an   = arow % NSEQ;
    const float* xbase = x + (size_t)ab * CDIM * NSEQ + an;

    const int bj = tid >> 1;
    const int bk = (tid & 1) * 4;
    const float* wbase = w + (size_t)(col0 + bj) * CDIM + bk;

    unsigned long long acc2[8][4];
    #pragma unroll
    for (int i = 0; i < 8; i++)
        #pragma unroll
        for (int t = 0; t < 4; t++) acc2[i][t] = 0ull;

    for (int k0 = 0; k0 < CDIM; k0 += 8) {
        #pragma unroll
        for (int l = 0; l < 4; l++) {
            float v = xbase[(size_t)(k0 + kb + 2*l) * NSEQ];
            *(float2*)&As2[kb + 2*l][2*ia] = make_float2(v, v);
        }
        float4 wv = *(const float4*)(wbase + k0);
        Bs[bk+0][bj] = wv.x; Bs[bk+1][bj] = wv.y;
        Bs[bk+2][bj] = wv.z; Bs[bk+3][bj] = wv.w;
        __syncthreads();
        #pragma unroll
        for (int kk = 0; kk < 8; kk++) {
            const unsigned long long* pa =
                (const unsigned long long*)&As2[kk][ty * 16];
            const unsigned long long* pb =
                (const unsigned long long*)&Bs[kk][tx * 8];
            unsigned long long a2[8], b2[4];
            #pragma unroll
            for (int i = 0; i < 8; i++) a2[i] = pa[i];
            #pragma unroll
            for (int t = 0; t < 4; t++) b2[t] = pb[t];
            #pragma unroll
            for (int i = 0; i < 8; i++)
                #pragma unroll
                for (int t = 0; t < 4; t++)
                    FMA_X2(acc2[i][t], a2[i], b2[t]);
        }
        __syncthreads();
    }
    #pragma unroll
    for (int i = 0; i < 8; i++) {
        size_t row = (size_t)(row0 + ty*8 + i);
        float* orow = g_qkv + row * K3 + col0 + tx*8;
        *(float4*)(orow)     = make_float4(ull_lo(acc2[i][0]), ull_hi(acc2[i][0]),
                                           ull_lo(acc2[i][1]), ull_hi(acc2[i][1]));
        *(float4*)(orow + 4) = make_float4(ull_lo(acc2[i][2]), ull_hi(acc2[i][2]),
                                           ull_lo(acc2[i][3]), ull_hi(acc2[i][3]));
    }
}

// =====================================================================
// GEMM 2 (HMMA, concatenated-K split; proven round 9, verbatim)
// =====================================================================
__global__ __launch_bounds__(256) void gemm2_mma(const float* __restrict__ bias,
                                                 float* __restrict__ gOut) {
    __shared__ __align__(16) __half sMem[2][2][128 * RP];   // 40960 B
    const int tid = threadIdx.x, lane = tid & 31, wid = tid >> 5;
    const int wm = wid & 3, wn = wid >> 2;
    const int row0 = blockIdx.x * 128, col0 = blockIdx.y * 128;

    const int lrow = tid >> 1, lhalf = tid & 1;
    const __half* gA = g_a2 + (size_t)(row0 + lrow) * K2CAT + lhalf * 16;
    const __half* gB = g_b2 + (size_t)(col0 + lrow) * K2CAT + lhalf * 16;

    uint4 ra0, ra1, rb0, rb1;
    auto loadRegs = [&](int c) {
        const uint4* pa = (const uint4*)(gA + c * 32);
        ra0 = pa[0]; ra1 = pa[1];
        const uint4* pb = (const uint4*)(gB + c * 32);
        rb0 = pb[0]; rb1 = pb[1];
    };

    float acc[2][8][4] = {};
    const int qrow = lane >> 2;          // 0..7
    const int qk2  = (lane & 3) * 2;     // 0,2,4,6
    const int K_ITERS = K2CAT / 32;      // 72

    loadRegs(0);

    for (int c = 0; c < K_ITERS; c++) {
        const int s = c & 1;
        {
            uint4* d = (uint4*)(&sMem[s][0][lrow * RP + lhalf * 16]);
            d[0] = ra0; d[1] = ra1;
            uint4* e = (uint4*)(&sMem[s][1][lrow * RP + lhalf * 16]);
            e[0] = rb0; e[1] = rb1;
        }
        __syncthreads();
        if (c + 1 < K_ITERS) loadRegs(c + 1);

        const __half* As = sMem[s][0];
        const __half* Bs = sMem[s][1];
        #pragma unroll
        for (int ksub = 0; ksub < 2; ksub++) {
            const int kb2 = ksub * 16 + qk2;
            uint32_t a[2][4];
            #pragma unroll
            for (int mt = 0; mt < 2; mt++) {
                const int ra = wm * 32 + mt * 16 + qrow;
                a[mt][0] = *(const uint32_t*)(As + ra * RP + kb2);
                a[mt][1] = *(const uint32_t*)(As + (ra + 8) * RP + kb2);
                a[mt][2] = *(const uint32_t*)(As + ra * RP + kb2 + 8);
                a[mt][3] = *(const uint32_t*)(As + (ra + 8) * RP + kb2 + 8);
            }
            #pragma unroll
            for (int nt = 0; nt < 8; nt++) {
                const int rb = wn * 64 + nt * 8 + qrow;
                const uint32_t b0 = *(const uint32_t*)(Bs + rb * RP + kb2);
                const uint32_t b1 = *(const uint32_t*)(Bs + rb * RP + kb2 + 8);
                MMA16816(acc[0][nt], a[0], b0, b1);
                MMA16816(acc[1][nt], a[1], b0, b1);
            }
        }
    }

    // transposed epilogue (+bias) through smem
    const int qcol = (lane & 3) * 2;
    float* T = (float*)sMem;   // [64][132] floats = 33792 B < 40960
    __syncthreads();
    #pragma unroll
    for (int half = 0; half < 2; half++) {
        if ((wm >> 1) == half) {
            const int mb = wm * 32 - half * 64;    // 0 or 32
            #pragma unroll
            for (int mt = 0; mt < 2; mt++) {
                const int ml = mb + mt * 16 + qrow;
                #pragma unroll
                for (int nt = 0; nt < 8; nt++) {
                    const int cl = wn * 64 + nt * 8 + qcol;
                    T[ml * 132 + cl]           = acc[mt][nt][0];
                    T[ml * 132 + cl + 1]       = acc[mt][nt][1];
                    T[(ml + 8) * 132 + cl]     = acc[mt][nt][2];
                    T[(ml + 8) * 132 + cl + 1] = acc[mt][nt][3];
                }
            }
        }
        __syncthreads();
        const int mloc = tid & 63;
        const int m = row0 + half * 64 + mloc;
        const int bb = m / NSEQ, nn = m % NSEQ;
        const int cbase = tid >> 6;
        #pragma unroll 4
        for (int cc = 0; cc < 32; cc++) {
            const int cl = cbase * 32 + cc;
            const int col = col0 + cl;
            gOut[((size_t)bb * CDIM + col) * NSEQ + nn] = T[mloc * 132 + cl] + __ldg(bias + col);
        }
        __syncthreads();
    }
}

// =====================================================================
// Split conversion for w_proj: g_b2 rows = [B0 | B1(residual) | B0]
// =====================================================================
__global__ __launch_bounds__(256) void conv_w2_kernel(const float* __restrict__ w) {
    int idx = blockIdx.x * 256 + threadIdx.x;
    int r = idx / CDIM, c = idx % CDIM;
    float val = w[idx];
    __half h0 = __float2half_rn(val);
    __half h1 = __float2half_rn(val - __half2float(h0));
    size_t base = (size_t)r * K2CAT;
    g_b2[base + c] = h0; g_b2[base + 768 + c] = h1; g_b2[base + 1536 + c] = h0;
}

// =====================================================================
// Binarize q / k (proven)
// =====================================================================
__global__ __launch_bounds__(256) void qk_binarize_kernel() {
    const int bh = blockIdx.x;
    const int which = blockIdx.y;
    const int b = bh / NHEAD, h = bh % NHEAD;
    unsigned long long* bits = which ? g_kbits : g_qbits;
    float sum = 0.f;
    for (int n = threadIdx.x; n < NSEQ; n += 256) {
        const float4* p = (const float4*)(g_qkv + (size_t)(b*NSEQ + n) * K3
                                          + which * CDIM + h * HDIM);
        unsigned long long m = 0ull;
        #pragma unroll
        for (int i = 0; i < 16; i++) {
            float4 v = p[i];
            sum += fabsf(v.x) + fabsf(v.y) + fabsf(v.z) + fabsf(v.w);
            if (v.x >= 0.f) m |= 1ull << (4*i + 0);
            if (v.y >= 0.f) m |= 1ull << (4*i + 1);
            if (v.z >= 0.f) m |= 1ull << (4*i + 2);
            if (v.w >= 0.f) m |= 1ull << (4*i + 3);
        }
        bits[bh * NSEQ + n] = m;
    }
    __shared__ float red[256];
    red[threadIdx.x] = sum;
    __syncthreads();
    for (int s = 128; s > 0; s >>= 1) {
        if (threadIdx.x < s) red[threadIdx.x] += red[threadIdx.x + s];
        __syncthreads();
    }
    if (threadIdx.x == 0) {
        float sm2 = red[0] / (float)(NSEQ * HDIM);
        (which ? g_sk : g_sq)[bh] = sm2;
    }
}

// =====================================================================
// Quantize V (proven)
// =====================================================================
__global__ __launch_bounds__(256) void v_quant_kernel() {
    const int bh = blockIdx.x;
    const int b = bh / NHEAD, h = bh % NHEAD;
    __shared__ float colmax[4][HDIM];
    __shared__ float s_s[HDIM];
    const int dd = threadIdx.x & 63, part = threadIdx.x >> 6;
    float mx = 0.f;
    for (int n = part; n < NSEQ; n += 4) {
        float v = g_qkv[(size_t)(b*NSEQ + n) * K3 + 2*CDIM + h*HDIM + dd];
        mx = fmaxf(mx, fabsf(v));
    }
    colmax[part][dd] = mx;
    __syncthreads();
    if (part == 0) {
        float m = fmaxf(fmaxf(colmax[0][dd], colmax[1][dd]),
                        fmaxf(colmax[2][dd], colmax[3][dd]));
        float s = 127.0f / (m + 1e-6f);
        s_s[dd] = s;
        g_vinv[bh * HDIM + dd] = 1.0f / (s + 1e-6f);
    }
    __syncthreads();
    for (int idx = threadIdx.x; idx < NSEQ * HDIM; idx += 256) {
        int n = idx >> 6, d2 = idx & 63;
        float v = g_qkv[(size_t)(b*NSEQ + n) * K3 + 2*CDIM + h*HDIM + d2];
        int r = (int)rintf(v * s_s[d2]);
        g_v8t[(size_t)bh * HDIM * NSEQ + (size_t)d2 * NSEQ + n] = (signed char)r;
    }
}

// =====================================================================
// Attention (proven; epilogue writes fp16 split triplet to g_a2)
// =====================================================================
__global__ __launch_bounds__(256) void attention_kernel() {
    __shared__ unsigned long long s_kb[NSEQ];
    __shared__ unsigned int s_v8[HDIM * 145];
    __shared__ float s_vinv[HDIM];
    __shared__ unsigned int s_p8[8][NSEQ/4];
    const int bh = blockIdx.x;
    const int rg = blockIdx.y;
    const int b = bh / NHEAD, h = bh % NHEAD;
    const int tid = threadIdx.x, lane = tid & 31, warp = tid >> 5;

    for (int i = tid; i < NSEQ; i += 256) s_kb[i] = g_kbits[bh * NSEQ + i];
    const unsigned int* vsrc = (const unsigned int*)(g_v8t + (size_t)bh * HDIM * NSEQ);
    for (int i = tid; i < HDIM * (NSEQ/4); i += 256) {
        int d = i / (NSEQ/4), mm = i % (NSEQ/4);
        s_v8[d * 145 + mm] = vsrc[i];
    }
    if (tid < HDIM) s_vinv[tid] = g_vinv[bh * HDIM + tid];
    __syncthreads();

    const float c0 = g_sq[bh] * g_sk[bh] * 0.125f;

    for (int r = warp; r < 192; r += 8) {
        const int n = rg * 192 + r;
        const unsigned long long qb = g_qbits[bh * NSEQ + n];
        float ev[18];
        float mx = -1e30f;
        #pragma unroll
        for (int jj = 0; jj < 18; jj++) {
            int j = lane + jj * 32;
            int pc = __popcll(qb ^ s_kb[j]);
            float sc = c0 * (float)(64 - 2 * pc);
            ev[jj] = sc;
            mx = fmaxf(mx, sc);
        }
        #pragma unroll
        for (int o = 16; o; o >>= 1) mx = fmaxf(mx, __shfl_xor_sync(0xffffffffu, mx, o));
        float sum = 0.f;
        #pragma unroll
        for (int jj = 0; jj < 18; jj++) {
            float e = expf(ev[jj] - mx);
            ev[jj] = e;
            sum += e;
        }
        #pragma unroll
        for (int o = 16; o; o >>= 1) sum += __shfl_xor_sync(0xffffffffu, sum, o);
        const float inv = 1.0f / sum;
        unsigned char* pb = (unsigned char*)s_p8[warp];
        #pragma unroll
        for (int jj = 0; jj < 18; jj++) {
            int j = lane + jj * 32;
            float p  = ev[jj] * inv;
            float pq = rintf(p * 255.0f);
            pq = fminf(fmaxf(pq, 0.0f), 255.0f);
            pb[j] = (unsigned char)pq;
        }
        __syncwarp();
        const unsigned int* prow = s_p8[warp];
        #pragma unroll
        for (int dp = 0; dp < 2; dp++) {
            int d = lane + dp * 32;
            const unsigned int* vcol = &s_v8[d * 145];
            int acc = 0;
            #pragma unroll 8
            for (int mm = 0; mm < NSEQ/4; mm++) {
                asm("dp4a.u32.s32 %0, %1, %2, %0;"
                    : "+r"(acc) : "r"(prow[mm]), "r"(vcol[mm]));
            }
            float val = (float)acc * (1.0f/255.0f) * s_vinv[d];
            __half h0 = __float2half_rn(val);
            __half h1 = __float2half_rn(val - __half2float(h0));
            size_t base = (size_t)(b * NSEQ + n) * K2CAT + h * HDIM + d;
            g_a2[base] = h0; g_a2[base + 768] = h0; g_a2[base + 1536] = h1;
        }
        __syncwarp();
    }
}

// =====================================================================
extern "C" void kernel_launch(void* const* d_in, const int* in_sizes, int n_in,
                              void* d_out, int out_size) {
    const float* x      = (const float*)d_in[0];
    const float* w_qkv  = (const float*)d_in[1];
    const float* w_proj = (const float*)d_in[2];
    const float* b_proj = (const float*)d_in[3];
    float* out = (float*)d_out;
    (void)in_sizes; (void)n_in; (void)out_size;

    gemm_qkv_kernel <<<dim3(MROWS/128, K3/128), 256>>>(x, w_qkv);   // fp32x2 exact
    qk_binarize_kernel<<<dim3(BH, 2), 256>>>();
    v_quant_kernel  <<<BH, 256>>>();
    attention_kernel<<<dim3(BH, 3), 256>>>();
    conv_w2_kernel  <<<(CDIM * CDIM) / 256, 256>>>(w_proj);
    gemm2_mma       <<<dim3(MROWS/128, CDIM/128), 256>>>(b_proj, out);  // HMMA split
}

// round 14
// speedup vs baseline: 1.0886x; 1.0886x over previous
#include <cuda_runtime.h>
#include <cuda_fp16.h>
#include <cstdint>

#define BATCH 16
#define CDIM  768
#define NSEQ  576
#define NHEAD 12
#define HDIM  64
#define BH    (BATCH*NHEAD)     // 192
#define MROWS (BATCH*NSEQ)      // 9216
#define K3    (3*CDIM)          // 2304
#define K2CAT 2304              // GEMM2 concatenated K (3 x 768)

// ---------------- static device scratch ----------------
__device__ __align__(128) float  g_qkv[(size_t)MROWS * K3];        // 85 MB
__device__ __align__(128) __half g_a2[(size_t)MROWS * K2CAT];      // attn out split 42.5 MB
__device__ __align__(128) __half g_b2[(size_t)CDIM  * K2CAT];      // w_proj split 3.4 MB
__device__ unsigned long long g_qbits[BH * NSEQ];
__device__ unsigned long long g_kbits[BH * NSEQ];
__device__ float              g_sq[BH];
__device__ float              g_sk[BH];
__device__ __align__(16) signed char g_v8t[(size_t)BH * HDIM * NSEQ];
__device__ float              g_vinv[BH * HDIM];

// ---------------- helpers ----------------
#define MMA16816(d, a, b0_, b1_) \
    asm volatile("mma.sync.aligned.m16n8k16.row.col.f32.f16.f16.f32 " \
        "{%0,%1,%2,%3}, {%4,%5,%6,%7}, {%8,%9}, {%0,%1,%2,%3};" \
        : "+f"((d)[0]),"+f"((d)[1]),"+f"((d)[2]),"+f"((d)[3]) \
        : "r"((a)[0]),"r"((a)[1]),"r"((a)[2]),"r"((a)[3]), "r"(b0_),"r"(b1_))

#define RP 40   // smem row pitch in fp16 elements (GEMM2)

// =====================================================================
// GEMM 1 (FFMA, proven exact, at FFMA roofline):
// qkv[m, j] = sum_c x[b,c,n] * w_qkv[j,c]
// =====================================================================
__global__ __launch_bounds__(256) void gemm_qkv_kernel(const float* __restrict__ x,
                                                       const float* __restrict__ w) {
    __shared__ float As[8][128];
    __shared__ float Bs[8][128];
    const int tid  = threadIdx.x;
    const int row0 = blockIdx.x * 128;
    const int col0 = blockIdx.y * 128;
    const int tx = tid & 15, ty = tid >> 4;

    const int ia   = tid & 127;
    const int kb   = tid >> 7;
    const int arow = row0 + ia;
    const int ab   = arow / NSEQ;
    const int an   = arow % NSEQ;
    const float* xbase = x + (size_t)ab * CDIM * NSEQ + an;

    const int bj = tid >> 1;
    const int bk = (tid & 1) * 4;
    const float* wbase = w + (size_t)(col0 + bj) * CDIM + bk;

    float acc[8][8];
    #pragma unroll
    for (int i = 0; i < 8; i++)
        #pragma unroll
        for (int j = 0; j < 8; j++) acc[i][j] = 0.f;

    for (int k0 = 0; k0 < CDIM; k0 += 8) {
        #pragma unroll
        for (int l = 0; l < 4; l++)
            As[kb + 2*l][ia] = xbase[(size_t)(k0 + kb + 2*l) * NSEQ];
        float4 wv = *(const float4*)(wbase + k0);
        Bs[bk+0][bj] = wv.x; Bs[bk+1][bj] = wv.y;
        Bs[bk+2][bj] = wv.z; Bs[bk+3][bj] = wv.w;
        __syncthreads();
        #pragma unroll
        for (int kk = 0; kk < 8; kk++) {
            float4 a0 = *(const float4*)&As[kk][ty*8];
            float4 a1 = *(const float4*)&As[kk][ty*8 + 4];
            float4 b0 = *(const float4*)&Bs[kk][tx*8];
            float4 b1 = *(const float4*)&Bs[kk][tx*8 + 4];
            float a[8] = {a0.x,a0.y,a0.z,a0.w,a1.x,a1.y,a1.z,a1.w};
            float bb[8] = {b0.x,b0.y,b0.z,b0.w,b1.x,b1.y,b1.z,b1.w};
            #pragma unroll
            for (int i = 0; i < 8; i++)
                #pragma unroll
                for (int j = 0; j < 8; j++)
                    acc[i][j] = fmaf(a[i], bb[j], acc[i][j]);
        }
        __syncthreads();
    }
    #pragma unroll
    for (int i = 0; i < 8; i++) {
        size_t row = (size_t)(row0 + ty*8 + i);
        float* orow = g_qkv + row * K3 + col0 + tx*8;
        *(float4*)(orow)     = make_float4(acc[i][0],acc[i][1],acc[i][2],acc[i][3]);
        *(float4*)(orow + 4) = make_float4(acc[i][4],acc[i][5],acc[i][6],acc[i][7]);
    }
}

// =====================================================================
// GEMM 2 (HMMA, concatenated-K split; proven round 9, verbatim)
// =====================================================================
__global__ __launch_bounds__(256) void gemm2_mma(const float* __restrict__ bias,
                                                 float* __restrict__ gOut) {
    __shared__ __align__(16) __half sMem[2][2][128 * RP];   // 40960 B
    const int tid = threadIdx.x, lane = tid & 31, wid = tid >> 5;
    const int wm = wid & 3, wn = wid >> 2;
    const int row0 = blockIdx.x * 128, col0 = blockIdx.y * 128;

    const int lrow = tid >> 1, lhalf = tid & 1;
    const __half* gA = g_a2 + (size_t)(row0 + lrow) * K2CAT + lhalf * 16;
    const __half* gB = g_b2 + (size_t)(col0 + lrow) * K2CAT + lhalf * 16;

    uint4 ra0, ra1, rb0, rb1;
    auto loadRegs = [&](int c) {
        const uint4* pa = (const uint4*)(gA + c * 32);
        ra0 = pa[0]; ra1 = pa[1];
        const uint4* pb = (const uint4*)(gB + c * 32);
        rb0 = pb[0]; rb1 = pb[1];
    };

    float acc[2][8][4] = {};
    const int qrow = lane >> 2;          // 0..7
    const int qk2  = (lane & 3) * 2;     // 0,2,4,6
    const int K_ITERS = K2CAT / 32;      // 72

    loadRegs(0);

    for (int c = 0; c < K_ITERS; c++) {
        const int s = c & 1;
        {
            uint4* d = (uint4*)(&sMem[s][0][lrow * RP + lhalf * 16]);
            d[0] = ra0; d[1] = ra1;
            uint4* e = (uint4*)(&sMem[s][1][lrow * RP + lhalf * 16]);
            e[0] = rb0; e[1] = rb1;
        }
        __syncthreads();
        if (c + 1 < K_ITERS) loadRegs(c + 1);

        const __half* As = sMem[s][0];
        const __half* Bs = sMem[s][1];
        #pragma unroll
        for (int ksub = 0; ksub < 2; ksub++) {
            const int kb2 = ksub * 16 + qk2;
            uint32_t a[2][4];
            #pragma unroll
            for (int mt = 0; mt < 2; mt++) {
                const int ra = wm * 32 + mt * 16 + qrow;
                a[mt][0] = *(const uint32_t*)(As + ra * RP + kb2);
                a[mt][1] = *(const uint32_t*)(As + (ra + 8) * RP + kb2);
                a[mt][2] = *(const uint32_t*)(As + ra * RP + kb2 + 8);
                a[mt][3] = *(const uint32_t*)(As + (ra + 8) * RP + kb2 + 8);
            }
            #pragma unroll
            for (int nt = 0; nt < 8; nt++) {
                const int rb = wn * 64 + nt * 8 + qrow;
                const uint32_t b0 = *(const uint32_t*)(Bs + rb * RP + kb2);
                const uint32_t b1 = *(const uint32_t*)(Bs + rb * RP + kb2 + 8);
                MMA16816(acc[0][nt], a[0], b0, b1);
                MMA16816(acc[1][nt], a[1], b0, b1);
            }
        }
    }

    // transposed epilogue (+bias) through smem
    const int qcol = (lane & 3) * 2;
    float* T = (float*)sMem;   // [64][132] floats = 33792 B < 40960
    __syncthreads();
    #pragma unroll
    for (int half = 0; half < 2; half++) {
        if ((wm >> 1) == half) {
            const int mb = wm * 32 - half * 64;    // 0 or 32
            #pragma unroll
            for (int mt = 0; mt < 2; mt++) {
                const int ml = mb + mt * 16 + qrow;
                #pragma unroll
                for (int nt = 0; nt < 8; nt++) {
                    const int cl = wn * 64 + nt * 8 + qcol;
                    T[ml * 132 + cl]           = acc[mt][nt][0];
                    T[ml * 132 + cl + 1]       = acc[mt][nt][1];
                    T[(ml + 8) * 132 + cl]     = acc[mt][nt][2];
                    T[(ml + 8) * 132 + cl + 1] = acc[mt][nt][3];
                }
            }
        }
        __syncthreads();
        const int mloc = tid & 63;
        const int m = row0 + half * 64 + mloc;
        const int bb = m / NSEQ, nn = m % NSEQ;
        const int cbase = tid >> 6;
        #pragma unroll 4
        for (int cc = 0; cc < 32; cc++) {
            const int cl = cbase * 32 + cc;
            const int col = col0 + cl;
            gOut[((size_t)bb * CDIM + col) * NSEQ + nn] = T[mloc * 132 + cl] + __ldg(bias + col);
        }
        __syncthreads();
    }
}

// =====================================================================
// Split conversion for w_proj: g_b2 rows = [B0 | B1(residual) | B0]
// =====================================================================
__global__ __launch_bounds__(256) void conv_w2_kernel(const float* __restrict__ w) {
    int idx = blockIdx.x * 256 + threadIdx.x;
    int r = idx / CDIM, c = idx % CDIM;
    float val = w[idx];
    __half h0 = __float2half_rn(val);
    __half h1 = __float2half_rn(val - __half2float(h0));
    size_t base = (size_t)r * K2CAT;
    g_b2[base + c] = h0; g_b2[base + 768 + c] = h1; g_b2[base + 1536 + c] = h0;
}

// =====================================================================
// Binarize q / k (proven)
// =====================================================================
__global__ __launch_bounds__(256) void qk_binarize_kernel() {
    const int bh = blockIdx.x;
    const int which = blockIdx.y;
    const int b = bh / NHEAD, h = bh % NHEAD;
    unsigned long long* bits = which ? g_kbits : g_qbits;
    float sum = 0.f;
    for (int n = threadIdx.x; n < NSEQ; n += 256) {
        const float4* p = (const float4*)(g_qkv + (size_t)(b*NSEQ + n) * K3
                                          + which * CDIM + h * HDIM);
        unsigned long long m = 0ull;
        #pragma unroll
        for (int i = 0; i < 16; i++) {
            float4 v = p[i];
            sum += fabsf(v.x) + fabsf(v.y) + fabsf(v.z) + fabsf(v.w);
            if (v.x >= 0.f) m |= 1ull << (4*i + 0);
            if (v.y >= 0.f) m |= 1ull << (4*i + 1);
            if (v.z >= 0.f) m |= 1ull << (4*i + 2);
            if (v.w >= 0.f) m |= 1ull << (4*i + 3);
        }
        bits[bh * NSEQ + n] = m;
    }
    __shared__ float red[256];
    red[threadIdx.x] = sum;
    __syncthreads();
    for (int s = 128; s > 0; s >>= 1) {
        if (threadIdx.x < s) red[threadIdx.x] += red[threadIdx.x + s];
        __syncthreads();
    }
    if (threadIdx.x == 0) {
        float sm2 = red[0] / (float)(NSEQ * HDIM);
        (which ? g_sk : g_sq)[bh] = sm2;
    }
}

// =====================================================================
// Quantize V (proven)
// =====================================================================
__global__ __launch_bounds__(256) void v_quant_kernel() {
    const int bh = blockIdx.x;
    const int b = bh / NHEAD, h = bh % NHEAD;
    __shared__ float colmax[4][HDIM];
    __shared__ float s_s[HDIM];
    const int dd = threadIdx.x & 63, part = threadIdx.x >> 6;
    float mx = 0.f;
    for (int n = part; n < NSEQ; n += 4) {
        float v = g_qkv[(size_t)(b*NSEQ + n) * K3 + 2*CDIM + h*HDIM + dd];
        mx = fmaxf(mx, fabsf(v));
    }
    colmax[part][dd] = mx;
    __syncthreads();
    if (part == 0) {
        float m = fmaxf(fmaxf(colmax[0][dd], colmax[1][dd]),
                        fmaxf(colmax[2][dd], colmax[3][dd]));
        float s = 127.0f / (m + 1e-6f);
        s_s[dd] = s;
        g_vinv[bh * HDIM + dd] = 1.0f / (s + 1e-6f);
    }
    __syncthreads();
    for (int idx = threadIdx.x; idx < NSEQ * HDIM; idx += 256) {
        int n = idx >> 6, d2 = idx & 63;
        float v = g_qkv[(size_t)(b*NSEQ + n) * K3 + 2*CDIM + h*HDIM + d2];
        int r = (int)rintf(v * s_s[d2]);
        g_v8t[(size_t)bh * HDIM * NSEQ + (size_t)d2 * NSEQ + n] = (signed char)r;
    }
}

// =====================================================================
// Attention with 65-entry exp TABLE (softmax shift-invariance:
// p_j = E[pc_j] / sum E[pc_j], E[i] = exp(-2*c0*i), c0 >= 0).
// Removes 63.7M expf (MUFU-bound) -> LDS lookups. Epilogue: fp16 split
// triplet into g_a2 (proven round 9).
// =====================================================================
__global__ __launch_bounds__(256) void attention_kernel() {
    __shared__ unsigned long long s_kb[NSEQ];
    __shared__ unsigned int s_v8[HDIM * 145];
    __shared__ float s_vinv[HDIM];
    __shared__ unsigned int s_p8[8][NSEQ/4];
    __shared__ float s_E[65];
    const int bh = blockIdx.x;
    const int rg = blockIdx.y;
    const int b = bh / NHEAD, h = bh % NHEAD;
    const int tid = threadIdx.x, lane = tid & 31, warp = tid >> 5;

    for (int i = tid; i < NSEQ; i += 256) s_kb[i] = g_kbits[bh * NSEQ + i];
    const unsigned int* vsrc = (const unsigned int*)(g_v8t + (size_t)bh * HDIM * NSEQ);
    for (int i = tid; i < HDIM * (NSEQ/4); i += 256) {
        int d = i / (NSEQ/4), mm = i % (NSEQ/4);
        s_v8[d * 145 + mm] = vsrc[i];
    }
    if (tid < HDIM) s_vinv[tid] = g_vinv[bh * HDIM + tid];
    if (tid < 65) {
        float c0 = g_sq[bh] * g_sk[bh] * 0.125f;
        s_E[tid] = expf(-2.0f * c0 * (float)tid);
    }
    __syncthreads();

    for (int r = warp; r < 192; r += 8) {
        const int n = rg * 192 + r;
        const unsigned long long qb = g_qbits[bh * NSEQ + n];
        float ev[18];
        float sum = 0.f;
        #pragma unroll
        for (int jj = 0; jj < 18; jj++) {
            int j = lane + jj * 32;
            int pc = __popcll(qb ^ s_kb[j]);
            float e = s_E[pc];
            ev[jj] = e;
            sum += e;
        }
        #pragma unroll
        for (int o = 16; o; o >>= 1) sum += __shfl_xor_sync(0xffffffffu, sum, o);
        const float inv = 1.0f / sum;
        unsigned char* pb = (unsigned char*)s_p8[warp];
        #pragma unroll
        for (int jj = 0; jj < 18; jj++) {
            int j = lane + jj * 32;
            float p  = ev[jj] * inv;
            float pq = rintf(p * 255.0f);
            pq = fminf(fmaxf(pq, 0.0f), 255.0f);
            pb[j] = (unsigned char)pq;
        }
        __syncwarp();
        const unsigned int* prow = s_p8[warp];
        #pragma unroll
        for (int dp = 0; dp < 2; dp++) {
            int d = lane + dp * 32;
            const unsigned int* vcol = &s_v8[d * 145];
            int acc = 0;
            #pragma unroll 8
            for (int mm = 0; mm < NSEQ/4; mm++) {
                asm("dp4a.u32.s32 %0, %1, %2, %0;"
                    : "+r"(acc) : "r"(prow[mm]), "r"(vcol[mm]));
            }
            float val = (float)acc * (1.0f/255.0f) * s_vinv[d];
            __half h0 = __float2half_rn(val);
            __half h1 = __float2half_rn(val - __half2float(h0));
            size_t base = (size_t)(b * NSEQ + n) * K2CAT + h * HDIM + d;
            g_a2[base] = h0; g_a2[base + 768] = h0; g_a2[base + 1536] = h1;
        }
        __syncwarp();
    }
}

// =====================================================================
extern "C" void kernel_launch(void* const* d_in, const int* in_sizes, int n_in,
                              void* d_out, int out_size) {
    const float* x      = (const float*)d_in[0];
    const float* w_qkv  = (const float*)d_in[1];
    const float* w_proj = (const float*)d_in[2];
    const float* b_proj = (const float*)d_in[3];
    float* out = (float*)d_out;
    (void)in_sizes; (void)n_in; (void)out_size;

    gemm_qkv_kernel <<<dim3(MROWS/128, K3/128), 256>>>(x, w_qkv);   // exact FFMA
    conv_w2_kernel  <<<(CDIM * CDIM) / 256, 256>>>(w_proj);
    qk_binarize_kernel<<<dim3(BH, 2), 256>>>();
    v_quant_kernel  <<<BH, 256>>>();
    attention_kernel<<<dim3(BH, 3), 256>>>();
    gemm2_mma       <<<dim3(MROWS/128, CDIM/128), 256>>>(b_proj, out);  // HMMA split
}

// round 15
// speedup vs baseline: 1.1879x; 1.0912x over previous
#include <cuda_runtime.h>
#include <cuda_fp16.h>
#include <cstdint>

#define BATCH 16
#define CDIM  768
#define NSEQ  576
#define NHEAD 12
#define HDIM  64
#define BH    (BATCH*NHEAD)     // 192
#define MROWS (BATCH*NSEQ)      // 9216
#define K3    (3*CDIM)          // 2304
#define K2CAT 2304              // GEMM2 concatenated K (3 x 768)

// ---------------- static device scratch ----------------
__device__ __align__(128) float  g_qkv[(size_t)MROWS * K3];        // 85 MB
__device__ __align__(128) __half g_a2[(size_t)MROWS * K2CAT];      // attn out split 42.5 MB
__device__ __align__(128) __half g_b2[(size_t)CDIM  * K2CAT];      // w_proj split 3.4 MB
__device__ unsigned long long g_qbits[BH * NSEQ];
__device__ unsigned long long g_kbits[BH * NSEQ];
__device__ float              g_sq[BH];
__device__ float              g_sk[BH];
__device__ __align__(16) signed char g_v8t[(size_t)BH * HDIM * NSEQ];
__device__ float              g_vinv[BH * HDIM];

// ---------------- helpers ----------------
#define MMA16816(d, a, b0_, b1_) \
    asm volatile("mma.sync.aligned.m16n8k16.row.col.f32.f16.f16.f32 " \
        "{%0,%1,%2,%3}, {%4,%5,%6,%7}, {%8,%9}, {%0,%1,%2,%3};" \
        : "+f"((d)[0]),"+f"((d)[1]),"+f"((d)[2]),"+f"((d)[3]) \
        : "r"((a)[0]),"r"((a)[1]),"r"((a)[2]),"r"((a)[3]), "r"(b0_),"r"(b1_))

#define RP 40   // smem row pitch in fp16 elements (GEMM2)

// =====================================================================
// GEMM 1 (FFMA, proven exact, at FFMA roofline):
// qkv[m, j] = sum_c x[b,c,n] * w_qkv[j,c]
// =====================================================================
__global__ __launch_bounds__(256) void gemm_qkv_kernel(const float* __restrict__ x,
                                                       const float* __restrict__ w) {
    __shared__ float As[8][128];
    __shared__ float Bs[8][128];
    const int tid  = threadIdx.x;
    const int row0 = blockIdx.x * 128;
    const int col0 = blockIdx.y * 128;
    const int tx = tid & 15, ty = tid >> 4;

    const int ia   = tid & 127;
    const int kb   = tid >> 7;
    const int arow = row0 + ia;
    const int ab   = arow / NSEQ;
    const int an   = arow % NSEQ;
    const float* xbase = x + (size_t)ab * CDIM * NSEQ + an;

    const int bj = tid >> 1;
    const int bk = (tid & 1) * 4;
    const float* wbase = w + (size_t)(col0 + bj) * CDIM + bk;

    float acc[8][8];
    #pragma unroll
    for (int i = 0; i < 8; i++)
        #pragma unroll
        for (int j = 0; j < 8; j++) acc[i][j] = 0.f;

    for (int k0 = 0; k0 < CDIM; k0 += 8) {
        #pragma unroll
        for (int l = 0; l < 4; l++)
            As[kb + 2*l][ia] = xbase[(size_t)(k0 + kb + 2*l) * NSEQ];
        float4 wv = *(const float4*)(wbase + k0);
        Bs[bk+0][bj] = wv.x; Bs[bk+1][bj] = wv.y;
        Bs[bk+2][bj] = wv.z; Bs[bk+3][bj] = wv.w;
        __syncthreads();
        #pragma unroll
        for (int kk = 0; kk < 8; kk++) {
            float4 a0 = *(const float4*)&As[kk][ty*8];
            float4 a1 = *(const float4*)&As[kk][ty*8 + 4];
            float4 b0 = *(const float4*)&Bs[kk][tx*8];
            float4 b1 = *(const float4*)&Bs[kk][tx*8 + 4];
            float a[8] = {a0.x,a0.y,a0.z,a0.w,a1.x,a1.y,a1.z,a1.w};
            float bb[8] = {b0.x,b0.y,b0.z,b0.w,b1.x,b1.y,b1.z,b1.w};
            #pragma unroll
            for (int i = 0; i < 8; i++)
                #pragma unroll
                for (int j = 0; j < 8; j++)
                    acc[i][j] = fmaf(a[i], bb[j], acc[i][j]);
        }
        __syncthreads();
    }
    #pragma unroll
    for (int i = 0; i < 8; i++) {
        size_t row = (size_t)(row0 + ty*8 + i);
        float* orow = g_qkv + row * K3 + col0 + tx*8;
        *(float4*)(orow)     = make_float4(acc[i][0],acc[i][1],acc[i][2],acc[i][3]);
        *(float4*)(orow + 4) = make_float4(acc[i][4],acc[i][5],acc[i][6],acc[i][7]);
    }
}

// =====================================================================
// GEMM 2 (HMMA, concatenated-K split; proven round 9, verbatim)
// =====================================================================
__global__ __launch_bounds__(256) void gemm2_mma(const float* __restrict__ bias,
                                                 float* __restrict__ gOut) {
    __shared__ __align__(16) __half sMem[2][2][128 * RP];   // 40960 B
    const int tid = threadIdx.x, lane = tid & 31, wid = tid >> 5;
    const int wm = wid & 3, wn = wid >> 2;
    const int row0 = blockIdx.x * 128, col0 = blockIdx.y * 128;

    const int lrow = tid >> 1, lhalf = tid & 1;
    const __half* gA = g_a2 + (size_t)(row0 + lrow) * K2CAT + lhalf * 16;
    const __half* gB = g_b2 + (size_t)(col0 + lrow) * K2CAT + lhalf * 16;

    uint4 ra0, ra1, rb0, rb1;
    auto loadRegs = [&](int c) {
        const uint4* pa = (const uint4*)(gA + c * 32);
        ra0 = pa[0]; ra1 = pa[1];
        const uint4* pb = (const uint4*)(gB + c * 32);
        rb0 = pb[0]; rb1 = pb[1];
    };

    float acc[2][8][4] = {};
    const int qrow = lane >> 2;          // 0..7
    const int qk2  = (lane & 3) * 2;     // 0,2,4,6
    const int K_ITERS = K2CAT / 32;      // 72

    loadRegs(0);

    for (int c = 0; c < K_ITERS; c++) {
        const int s = c & 1;
        {
            uint4* d = (uint4*)(&sMem[s][0][lrow * RP + lhalf * 16]);
            d[0] = ra0; d[1] = ra1;
            uint4* e = (uint4*)(&sMem[s][1][lrow * RP + lhalf * 16]);
            e[0] = rb0; e[1] = rb1;
        }
        __syncthreads();
        if (c + 1 < K_ITERS) loadRegs(c + 1);

        const __half* As = sMem[s][0];
        const __half* Bs = sMem[s][1];
        #pragma unroll
        for (int ksub = 0; ksub < 2; ksub++) {
            const int kb2 = ksub * 16 + qk2;
            uint32_t a[2][4];
            #pragma unroll
            for (int mt = 0; mt < 2; mt++) {
                const int ra = wm * 32 + mt * 16 + qrow;
                a[mt][0] = *(const uint32_t*)(As + ra * RP + kb2);
                a[mt][1] = *(const uint32_t*)(As + (ra + 8) * RP + kb2);
                a[mt][2] = *(const uint32_t*)(As + ra * RP + kb2 + 8);
                a[mt][3] = *(const uint32_t*)(As + (ra + 8) * RP + kb2 + 8);
            }
            #pragma unroll
            for (int nt = 0; nt < 8; nt++) {
                const int rb = wn * 64 + nt * 8 + qrow;
                const uint32_t b0 = *(const uint32_t*)(Bs + rb * RP + kb2);
                const uint32_t b1 = *(const uint32_t*)(Bs + rb * RP + kb2 + 8);
                MMA16816(acc[0][nt], a[0], b0, b1);
                MMA16816(acc[1][nt], a[1], b0, b1);
            }
        }
    }

    // transposed epilogue (+bias) through smem
    const int qcol = (lane & 3) * 2;
    float* T = (float*)sMem;   // [64][132] floats = 33792 B < 40960
    __syncthreads();
    #pragma unroll
    for (int half = 0; half < 2; half++) {
        if ((wm >> 1) == half) {
            const int mb = wm * 32 - half * 64;    // 0 or 32
            #pragma unroll
            for (int mt = 0; mt < 2; mt++) {
                const int ml = mb + mt * 16 + qrow;
                #pragma unroll
                for (int nt = 0; nt < 8; nt++) {
                    const int cl = wn * 64 + nt * 8 + qcol;
                    T[ml * 132 + cl]           = acc[mt][nt][0];
                    T[ml * 132 + cl + 1]       = acc[mt][nt][1];
                    T[(ml + 8) * 132 + cl]     = acc[mt][nt][2];
                    T[(ml + 8) * 132 + cl + 1] = acc[mt][nt][3];
                }
            }
        }
        __syncthreads();
        const int mloc = tid & 63;
        const int m = row0 + half * 64 + mloc;
        const int bb = m / NSEQ, nn = m % NSEQ;
        const int cbase = tid >> 6;
        #pragma unroll 4
        for (int cc = 0; cc < 32; cc++) {
            const int cl = cbase * 32 + cc;
            const int col = col0 + cl;
            gOut[((size_t)bb * CDIM + col) * NSEQ + nn] = T[mloc * 132 + cl] + __ldg(bias + col);
        }
        __syncthreads();
    }
}

// =====================================================================
// Split conversion for w_proj: g_b2 rows = [B0 | B1(residual) | B0]
// =====================================================================
__global__ __launch_bounds__(256) void conv_w2_kernel(const float* __restrict__ w) {
    int idx = blockIdx.x * 256 + threadIdx.x;
    int r = idx / CDIM, c = idx % CDIM;
    float val = w[idx];
    __half h0 = __float2half_rn(val);
    __half h1 = __float2half_rn(val - __half2float(h0));
    size_t base = (size_t)r * K2CAT;
    g_b2[base + c] = h0; g_b2[base + 768 + c] = h1; g_b2[base + 1536 + c] = h0;
}

// =====================================================================
// Binarize q / k (proven)
// =====================================================================
__global__ __launch_bounds__(256) void qk_binarize_kernel() {
    const int bh = blockIdx.x;
    const int which = blockIdx.y;
    const int b = bh / NHEAD, h = bh % NHEAD;
    unsigned long long* bits = which ? g_kbits : g_qbits;
    float sum = 0.f;
    for (int n = threadIdx.x; n < NSEQ; n += 256) {
        const float4* p = (const float4*)(g_qkv + (size_t)(b*NSEQ + n) * K3
                                          + which * CDIM + h * HDIM);
        unsigned long long m = 0ull;
        #pragma unroll
        for (int i = 0; i < 16; i++) {
            float4 v = p[i];
            sum += fabsf(v.x) + fabsf(v.y) + fabsf(v.z) + fabsf(v.w);
            if (v.x >= 0.f) m |= 1ull << (4*i + 0);
            if (v.y >= 0.f) m |= 1ull << (4*i + 1);
            if (v.z >= 0.f) m |= 1ull << (4*i + 2);
            if (v.w >= 0.f) m |= 1ull << (4*i + 3);
        }
        bits[bh * NSEQ + n] = m;
    }
    __shared__ float red[256];
    red[threadIdx.x] = sum;
    __syncthreads();
    for (int s = 128; s > 0; s >>= 1) {
        if (threadIdx.x < s) red[threadIdx.x] += red[threadIdx.x + s];
        __syncthreads();
    }
    if (threadIdx.x == 0) {
        float sm2 = red[0] / (float)(NSEQ * HDIM);
        (which ? g_sk : g_sq)[bh] = sm2;
    }
}

// =====================================================================
// Quantize V — rewritten for latency: 1024 threads, 4-way MLP absmax,
// coalesced reads, packed u32 stores. Math identical to proven version.
// =====================================================================
__global__ __launch_bounds__(1024) void v_quant_kernel() {
    const int bh = blockIdx.x;
    const int b = bh / NHEAD, h = bh % NHEAD;
    __shared__ float red[16][HDIM];
    __shared__ float s_s[HDIM];
    const int tid = threadIdx.x;
    const int dd = tid & 63, part = tid >> 6;    // 16 parts
    const size_t base = (size_t)b * NSEQ * K3 + 2 * CDIM + (size_t)h * HDIM;

    // Phase A: absmax over n for each column d (4 independent chains)
    float m0 = 0.f, m1 = 0.f, m2 = 0.f, m3 = 0.f;
    #pragma unroll
    for (int n = part; n < NSEQ; n += 64) {
        m0 = fmaxf(m0, fabsf(g_qkv[base + (size_t)(n)      * K3 + dd]));
        m1 = fmaxf(m1, fabsf(g_qkv[base + (size_t)(n + 16) * K3 + dd]));
        m2 = fmaxf(m2, fabsf(g_qkv[base + (size_t)(n + 32) * K3 + dd]));
        m3 = fmaxf(m3, fabsf(g_qkv[base + (size_t)(n + 48) * K3 + dd]));
    }
    red[part][dd] = fmaxf(fmaxf(m0, m1), fmaxf(m2, m3));
    __syncthreads();
    if (tid < 64) {
        float m = 0.f;
        #pragma unroll
        for (int p = 0; p < 16; p++) m = fmaxf(m, red[p][tid]);
        float s = 127.0f / (m + 1e-6f);
        s_s[tid] = s;
        g_vinv[bh * HDIM + tid] = 1.0f / (s + 1e-6f);
    }
    __syncthreads();

    // Phase B: quantize, pack 4 n-bytes per u32, store [d][n/4]
    unsigned int* vdst = (unsigned int*)(g_v8t + (size_t)bh * HDIM * NSEQ);
    const float sc = s_s[dd];
    #pragma unroll
    for (int ng = part; ng < NSEQ / 4; ng += 16) {
        const int n0 = ng * 4;
        unsigned int pk = 0;
        #pragma unroll
        for (int j = 0; j < 4; j++) {
            float v = g_qkv[base + (size_t)(n0 + j) * K3 + dd];
            int r = (int)rintf(v * sc);
            pk |= ((unsigned int)(unsigned char)(signed char)r) << (8 * j);
        }
        vdst[dd * (NSEQ / 4) + ng] = pk;
    }
}

// =====================================================================
// Attention: exp TABLE (proven round 14) + fused dp4a loop (shared prow LDS).
// Epilogue writes fp16 split triplet to g_a2 (proven round 9).
// =====================================================================
__global__ __launch_bounds__(256) void attention_kernel() {
    __shared__ unsigned long long s_kb[NSEQ];
    __shared__ unsigned int s_v8[HDIM * 145];
    __shared__ float s_vinv[HDIM];
    __shared__ unsigned int s_p8[8][NSEQ/4];
    __shared__ float s_E[65];
    const int bh = blockIdx.x;
    const int rg = blockIdx.y;
    const int b = bh / NHEAD, h = bh % NHEAD;
    const int tid = threadIdx.x, lane = tid & 31, warp = tid >> 5;

    for (int i = tid; i < NSEQ; i += 256) s_kb[i] = g_kbits[bh * NSEQ + i];
    const unsigned int* vsrc = (const unsigned int*)(g_v8t + (size_t)bh * HDIM * NSEQ);
    for (int i = tid; i < HDIM * (NSEQ/4); i += 256) {
        int d = i / (NSEQ/4), mm = i % (NSEQ/4);
        s_v8[d * 145 + mm] = vsrc[i];
    }
    if (tid < HDIM) s_vinv[tid] = g_vinv[bh * HDIM + tid];
    if (tid < 65) {
        float c0 = g_sq[bh] * g_sk[bh] * 0.125f;
        s_E[tid] = expf(-2.0f * c0 * (float)tid);
    }
    __syncthreads();

    for (int r = warp; r < 192; r += 8) {
        const int n = rg * 192 + r;
        const unsigned long long qb = g_qbits[bh * NSEQ + n];
        float ev[18];
        float sum = 0.f;
        #pragma unroll
        for (int jj = 0; jj < 18; jj++) {
            int j = lane + jj * 32;
            int pc = __popcll(qb ^ s_kb[j]);
            float e = s_E[pc];
            ev[jj] = e;
            sum += e;
        }
        #pragma unroll
        for (int o = 16; o; o >>= 1) sum += __shfl_xor_sync(0xffffffffu, sum, o);
        const float inv = 1.0f / sum;
        unsigned char* pb = (unsigned char*)s_p8[warp];
        #pragma unroll
        for (int jj = 0; jj < 18; jj++) {
            int j = lane + jj * 32;
            float p  = ev[jj] * inv;
            float pq = rintf(p * 255.0f);
            pq = fminf(fmaxf(pq, 0.0f), 255.0f);
            pb[j] = (unsigned char)pq;
        }
        __syncwarp();
        const unsigned int* prow = s_p8[warp];
        const unsigned int* vcol0 = &s_v8[lane * 145];
        const unsigned int* vcol1 = &s_v8[(lane + 32) * 145];
        int acc0 = 0, acc1 = 0;
        #pragma unroll 8
        for (int mm = 0; mm < NSEQ/4; mm++) {
            unsigned int p = prow[mm];
            asm("dp4a.u32.s32 %0, %1, %2, %0;" : "+r"(acc0) : "r"(p), "r"(vcol0[mm]));
            asm("dp4a.u32.s32 %0, %1, %2, %0;" : "+r"(acc1) : "r"(p), "r"(vcol1[mm]));
        }
        #pragma unroll
        for (int dp = 0; dp < 2; dp++) {
            const int d = lane + dp * 32;
            const int acc = dp ? acc1 : acc0;
            float val = (float)acc * (1.0f/255.0f) * s_vinv[d];
            __half h0 = __float2half_rn(val);
            __half h1 = __float2half_rn(val - __half2float(h0));
            size_t base = (size_t)(b * NSEQ + n) * K2CAT + h * HDIM + d;
            g_a2[base] = h0; g_a2[base + 768] = h0; g_a2[base + 1536] = h1;
        }
        __syncwarp();
    }
}

// =====================================================================
extern "C" void kernel_launch(void* const* d_in, const int* in_sizes, int n_in,
                              void* d_out, int out_size) {
    const float* x      = (const float*)d_in[0];
    const float* w_qkv  = (const float*)d_in[1];
    const float* w_proj = (const float*)d_in[2];
    const float* b_proj = (const float*)d_in[3];
    float* out = (float*)d_out;
    (void)in_sizes; (void)n_in; (void)out_size;

    gemm_qkv_kernel <<<dim3(MROWS/128, K3/128), 256>>>(x, w_qkv);   // exact FFMA
    conv_w2_kernel  <<<(CDIM * CDIM) / 256, 256>>>(w_proj);
    qk_binarize_kernel<<<dim3(BH, 2), 256>>>();
    v_quant_kernel  <<<BH, 1024>>>();
    attention_kernel<<<dim3(BH, 3), 256>>>();
    gemm2_mma       <<<dim3(MROWS/128, CDIM/128), 256>>>(b_proj, out);  // HMMA split
}